// round 9
// baseline (speedup 1.0000x reference)
#include <cuda_runtime.h>
#include <math.h>

#define RS2 0.70710678f // 1/sqrt(2)

typedef unsigned long long u64;

// packed f32x2 FMA (lanewise fp32 fma): d = a*b + d
#define FMA2(d, a, b) asm("fma.rn.f32x2 %0, %1, %2, %0;" : "+l"(d) : "l"(a), "l"(b))

__device__ __forceinline__ u64 dup2(float w) {
    u64 r;
    asm("mov.b64 %0, {%1, %1};" : "=l"(r) : "r"(__float_as_uint(w)));
    return r;
}

// ---- scratch (device globals; no allocation allowed) ----
__device__ float g_s  [4*4*256*32*32];      // spikes (0/1)
__device__ float g_l1 [16*512*32*16];       // pre-BN level-1 coeffs
__device__ float g_l2 [16*1024*16*16];      // pre-BN level-2 coeffs
__device__ float g_rec[16*256*32*32];       // pre-BN reconstruction
__device__ float g_c1 [16*256*32*32];       // pre-BN conv1 out
__device__ float g_c2 [16*256*32*32];       // pre-BN conv2 out
// per-(channel, slot) partial (sum, sumsq) — fixed slots => deterministic
__device__ float2 g_part_fwd[512*8];
__device__ float2 g_part_mul[1024*16];
__device__ float2 g_part_inv[256*16];
__device__ float2 g_part_c1 [256*16];
__device__ float2 g_part_c2 [256*16];

// ============================================================
// K1: LIF over T + Haar along W + L1 gate + bn_fwd partials
// ============================================================
__global__ void k_lif_haarw(const float* __restrict__ x) {
    int blk = blockIdx.x, t = threadIdx.x;
    int idx = blk * 256 + t;
    int wp = idx & 15;
    int h  = (idx >> 4) & 31;
    int c  = (idx >> 9) & 255;
    int b  = idx >> 17;

    float v0 = 0.f, v1 = 0.f;
    float4 ps = make_float4(0.f, 0.f, 0.f, 0.f);
    #pragma unroll
    for (int tt = 0; tt < 4; tt++) {
        size_t base = ((((size_t)tt*4 + b)*256 + c)*32 + h)*32 + 2*wp;
        float2 xx = *reinterpret_cast<const float2*>(&x[base]);
        v0 += (xx.x - v0) * 0.5f;
        float s0 = (v0 >= 1.0f) ? 1.0f : 0.0f;
        v0 *= (1.0f - s0);
        v1 += (xx.y - v1) * 0.5f;
        float s1 = (v1 >= 1.0f) ? 1.0f : 0.0f;
        v1 *= (1.0f - s1);
        *reinterpret_cast<float2*>(&g_s[base]) = make_float2(s0, s1);

        float low  = RS2 * (s0 + s1);
        float high = RS2 * (s0 - s1);
        if (fabsf(low)  < 0.5f) low  = 0.f;
        if (fabsf(high) < 0.5f) high = 0.f;
        int tb = tt*4 + b;
        size_t l1b = (((size_t)tb*512 + c)*32 + h)*16 + wp;
        g_l1[l1b]          = low;
        g_l1[l1b + 131072] = high;
        ps.x += low;  ps.y += low*low;
        ps.z += high; ps.w += high*high;
    }
    #pragma unroll
    for (int off = 16; off; off >>= 1) {
        ps.x += __shfl_down_sync(0xffffffffu, ps.x, off);
        ps.y += __shfl_down_sync(0xffffffffu, ps.y, off);
        ps.z += __shfl_down_sync(0xffffffffu, ps.z, off);
        ps.w += __shfl_down_sync(0xffffffffu, ps.w, off);
    }
    __shared__ float4 wsum[8];
    if ((t & 31) == 0) wsum[t >> 5] = ps;
    __syncthreads();
    if (t == 0) {
        float4 a = wsum[0];
        #pragma unroll
        for (int i = 1; i < 8; i++) {
            float4 w4 = wsum[i];
            a.x += w4.x; a.y += w4.y; a.z += w4.z; a.w += w4.w;
        }
        int slot = ((blk >> 9) << 1) | (blk & 1);   // b*2 + hhalf
        int cc   = (blk >> 1) & 255;
        g_part_fwd[cc*8 + slot]         = make_float2(a.x, a.y);
        g_part_fwd[(256 + cc)*8 + slot] = make_float2(a.z, a.w);
    }
}

// ============================================================
// K2: inline bn_fwd stats + Haar along H + threshold + band gate
//     + bn_mul partials. block <-> (tb, c)
// ============================================================
__global__ void k_haarh_gate(const float* __restrict__ gf,
                             const float* __restrict__ bf) {
    int tb = blockIdx.x >> 8;
    int c  = blockIdx.x & 255;
    int t  = threadIdx.x;

    __shared__ float2 coef[2];
    if (t < 16) {
        int chn = (t < 8) ? c : 256 + c;
        float2 p = g_part_fwd[chn*8 + (t & 7)];
        float s = p.x, q = p.y;
        #pragma unroll
        for (int off = 4; off; off >>= 1) {
            s += __shfl_down_sync(0xffffu, s, off, 8);
            q += __shfl_down_sync(0xffffu, q, off, 8);
        }
        if ((t & 7) == 0) {
            float mean = s * (1.0f/8192.0f);
            float var  = q * (1.0f/8192.0f) - mean*mean;
            float a = gf[chn] * rsqrtf(var + 1e-5f);
            coef[t >> 3] = make_float2(a, bf[chn] - mean*a);
        }
    }
    __syncthreads();

    int v = t >> 4, w = t & 15;
    float alo = coef[0].x, clo = coef[0].y;
    float ahi = coef[1].x, chi = coef[1].y;

    size_t lo_base = ((size_t)tb*512 + c) * 512;
    size_t hi_base = lo_base + 131072;
    float a0 = g_l1[lo_base + (2*v  )*16 + w] * alo + clo;
    float a1 = g_l1[lo_base + (2*v+1)*16 + w] * alo + clo;
    float b0 = g_l1[hi_base + (2*v  )*16 + w] * ahi + chi;
    float b1 = g_l1[hi_base + (2*v+1)*16 + w] * ahi + chi;

    float LL = RS2 * (a0 + a1);
    float HL = RS2 * (a0 - a1);
    float LH = RS2 * (b0 + b1);
    float HH = RS2 * (b0 - b1);
    if (fabsf(LL) < 0.5f) LL = 0.f;
    if (fabsf(HL) < 0.5f) HL = 0.f;
    if (fabsf(LH) < 0.5f) LH = 0.f;
    if (fabsf(HH) < 0.5f) HH = 0.f;

    float4 vs = make_float4(LL, HL, LH, HH);
    float4 vq = make_float4(LL*LL, HL*HL, LH*LH, HH*HH);
    #pragma unroll
    for (int off = 16; off; off >>= 1) {
        vs.x += __shfl_down_sync(0xffffffffu, vs.x, off);
        vs.y += __shfl_down_sync(0xffffffffu, vs.y, off);
        vs.z += __shfl_down_sync(0xffffffffu, vs.z, off);
        vs.w += __shfl_down_sync(0xffffffffu, vs.w, off);
        vq.x += __shfl_down_sync(0xffffffffu, vq.x, off);
        vq.y += __shfl_down_sync(0xffffffffu, vq.y, off);
        vq.z += __shfl_down_sync(0xffffffffu, vq.z, off);
        vq.w += __shfl_down_sync(0xffffffffu, vq.w, off);
    }
    __shared__ float4 wS[8], wQ[8];
    __shared__ float4 flags;
    if ((t & 31) == 0) { wS[t >> 5] = vs; wQ[t >> 5] = vq; }
    __syncthreads();
    if (t == 0) {
        float4 S = wS[0], Q = wQ[0];
        #pragma unroll
        for (int i = 1; i < 8; i++) {
            float4 a = wS[i], b4 = wQ[i];
            S.x += a.x;  S.y += a.y;  S.z += a.z;  S.w += a.w;
            Q.x += b4.x; Q.y += b4.y; Q.z += b4.z; Q.w += b4.w;
        }
        const float inv = 1.0f / 256.0f;
        float4 f = make_float4(Q.x*inv > 0.01f ? 1.f : 0.f,
                               Q.y*inv > 0.02f ? 1.f : 0.f,
                               Q.z*inv > 0.02f ? 1.f : 0.f,
                               Q.w*inv > 0.05f ? 1.f : 0.f);
        flags = f;
        g_part_mul[(c      )*16 + tb] = make_float2(f.x*S.x, f.x*Q.x);
        g_part_mul[(c + 256)*16 + tb] = make_float2(f.y*S.y, f.y*Q.y);
        g_part_mul[(c + 512)*16 + tb] = make_float2(f.z*S.z, f.z*Q.z);
        g_part_mul[(c + 768)*16 + tb] = make_float2(f.w*S.w, f.w*Q.w);
    }
    __syncthreads();

    size_t ob = (((size_t)tb*1024 + c)*16 + v)*16 + w;
    g_l2[ob]          = LL * flags.x;
    g_l2[ob + 65536]  = HL * flags.y;
    g_l2[ob + 131072] = LH * flags.z;
    g_l2[ob + 196608] = HH * flags.w;
}

// ============================================================
// K3 (fused): bn_mul stats + 16x16 channel mix for all 4 subbands of a
// base group + inverse Haar butterfly + bn_inv partials.
// ============================================================
__global__ void k_mix_inv(const float* __restrict__ hw,
                          const float* __restrict__ gm,
                          const float* __restrict__ bm) {
    int tb = blockIdx.x >> 4;
    int gb = blockIdx.x & 15;
    int t  = threadIdx.x;

    __shared__ float Wsm[4][256];
    __shared__ float sc[64], of[64];
    __shared__ float2 wred[8][16];

    #pragma unroll
    for (int sb = 0; sb < 4; sb++)
        Wsm[sb][t] = hw[(4*sb + (gb >> 2)) * 256 + t];

    {
        int chl = t >> 2, j = t & 3;
        int sb = chl >> 4, d = chl & 15;
        int ch = sb*256 + gb*16 + d;
        float s = 0.f, q = 0.f;
        #pragma unroll
        for (int k = 0; k < 4; k++) {
            float2 p = g_part_mul[ch*16 + j + 4*k];
            s += p.x; q += p.y;
        }
        s += __shfl_down_sync(0xffffffffu, s, 2, 4);
        q += __shfl_down_sync(0xffffffffu, q, 2, 4);
        s += __shfl_down_sync(0xffffffffu, s, 1, 4);
        q += __shfl_down_sync(0xffffffffu, q, 1, 4);
        if (j == 0) {
            float mean = s * (1.0f/4096.0f);
            float var  = q * (1.0f/4096.0f) - mean*mean;
            float a = gm[ch] * rsqrtf(var + 1e-5f);
            sc[chl] = a;
            of[chl] = bm[ch] - mean*a;
        }
    }
    __syncthreads();

    float acc[4][16];
    #pragma unroll
    for (int sb = 0; sb < 4; sb++)
        #pragma unroll
        for (int k = 0; k < 16; k++) acc[sb][k] = 0.f;

    #pragma unroll
    for (int sb = 0; sb < 4; sb++) {
        size_t base = ((size_t)tb*1024 + sb*256 + gb*16) * 256 + t;
        #pragma unroll
        for (int d = 0; d < 16; d++) {
            float in = g_l2[base + (size_t)d*256] * sc[sb*16+d] + of[sb*16+d];
            #pragma unroll
            for (int k = 0; k < 16; k++) acc[sb][k] += in * Wsm[sb][d*16 + k];
        }
    }

    int v = t >> 4, w = t & 15;
    int warp = t >> 5;
    #pragma unroll
    for (int k = 0; k < 16; k++) {
        float LL = acc[0][k], HL = acc[1][k], LH = acc[2][k], HH = acc[3][k];
        float lo0 = RS2*(LL + HL), lo1 = RS2*(LL - HL);
        float hi0 = RS2*(LH + HH), hi1 = RS2*(LH - HH);
        float r00 = RS2*(lo0 + hi0), r01 = RS2*(lo0 - hi0);
        float r10 = RS2*(lo1 + hi1), r11 = RS2*(lo1 - hi1);

        size_t rb = (((size_t)tb*256 + gb*16 + k)*32 + 2*v)*32 + 2*w;
        *reinterpret_cast<float2*>(&g_rec[rb])      = make_float2(r00, r01);
        *reinterpret_cast<float2*>(&g_rec[rb + 32]) = make_float2(r10, r11);

        float s = r00 + r01 + r10 + r11;
        float q = r00*r00 + r01*r01 + r10*r10 + r11*r11;
        #pragma unroll
        for (int off = 16; off; off >>= 1) {
            s += __shfl_down_sync(0xffffffffu, s, off);
            q += __shfl_down_sync(0xffffffffu, q, off);
        }
        if ((t & 31) == 0) wred[warp][k] = make_float2(s, q);
    }
    __syncthreads();
    if (t < 16) {
        float S = 0.f, Q = 0.f;
        #pragma unroll
        for (int wd = 0; wd < 8; wd++) { S += wred[wd][t].x; Q += wred[wd][t].y; }
        g_part_inv[(gb*16 + t)*16 + tb] = make_float2(S, Q);
    }
}

// ============================================================
// K4 (fused conv): grouped 3x3 conv (FFMA2) + grouped 1x1 conv folded
// into the ky==1 leg (E_p = center-row pairs), sharing the smem staging.
// + bn_c1 and bn_c2 partials. Red arrays alias tileA (dead after phases).
// ============================================================
#define A_RS 36
#define A_CH (34 * A_RS)   // 1224
#define B_RS 32
#define B_CH (34 * B_RS)   // 1088

__global__ __launch_bounds__(512) void k_convs(const float* __restrict__ w2,
                                               const float* __restrict__ w1) {
    int im = blockIdx.x;
    int tb = im >> 4, nb = im & 15;
    __shared__ __align__(16) float tileA[4 * A_CH];  // 19584 B (reused for red)
    __shared__ __align__(16) float tileB[4 * B_CH];  // 17408 B
    __shared__ float Wsm[2304];                      //  9216 B
    __shared__ float Wsm1[256];                      //  1024 B
    int tid = threadIdx.x;
    int o = tid & 15, h = tid >> 4;

    for (int idx = tid; idx < 2304; idx += 512) Wsm[idx] = w2[idx];
    if (tid < 256) Wsm1[tid] = w1[tid];
    for (int idx = tid; idx < 4 * A_CH; idx += 512) tileA[idx] = 0.f;
    for (int idx = tid; idx < 4 * B_CH; idx += 512) tileB[idx] = 0.f;

    size_t sbase = ((size_t)tb*256 + nb*16) * 1024;

    u64 acc[16], acc1[16];
    #pragma unroll
    for (int p = 0; p < 16; p++) { acc[p] = 0ull; acc1[p] = 0ull; }

    for (int ph = 0; ph < 4; ph++) {
        __syncthreads();
        for (int idx4 = tid; idx4 < 1024; idx4 += 512) {
            int ii  = idx4 >> 8;
            int rem = idx4 & 255;
            int hh  = rem >> 3;
            int ww4 = (rem & 7) * 4;
            float4 val = *reinterpret_cast<const float4*>(
                &g_s[sbase + (size_t)(ph*4 + ii)*1024 + hh*32 + ww4]);
            float* dA = &tileA[ii*A_CH + (hh+1)*A_RS + ww4 + 1];
            dA[0] = val.x; dA[1] = val.y; dA[2] = val.z; dA[3] = val.w;
            *reinterpret_cast<float4*>(&tileB[ii*B_CH + (hh+1)*B_RS + ww4]) = val;
        }
        __syncthreads();

        #pragma unroll
        for (int ii = 0; ii < 4; ii++) {
            int ic = ph*4 + ii;
            u64 wpk[3][3];
            #pragma unroll
            for (int ky = 0; ky < 3; ky++)
                #pragma unroll
                for (int kx = 0; kx < 3; kx++)
                    wpk[ky][kx] = dup2(Wsm[o*144 + ic*9 + ky*3 + kx]);
            u64 w1pk = dup2(Wsm1[o*16 + ic]);

            #pragma unroll
            for (int ky = 0; ky < 3; ky++) {
                const u64* A64 = reinterpret_cast<const u64*>(
                    &tileA[ii*A_CH + (h + ky)*A_RS]);
                const u64* B64 = reinterpret_cast<const u64*>(
                    &tileB[ii*B_CH + (h + ky)*B_RS]);
                u64 sp = A64[0];
                #pragma unroll
                for (int p = 0; p < 16; p++) {
                    u64 e  = B64[p];
                    u64 sn = A64[p + 1];
                    FMA2(acc[p], wpk[ky][0], sp);
                    FMA2(acc[p], wpk[ky][1], e);
                    FMA2(acc[p], wpk[ky][2], sn);
                    if (ky == 1) FMA2(acc1[p], w1pk, e);   // 1x1 conv, center row
                    sp = sn;
                }
            }
        }
    }

    // stores + bn partials (red arrays alias tileA, which is now dead)
    __syncthreads();
    float2* red2 = reinterpret_cast<float2*>(tileA);        // [16][16]
    float2* red1 = reinterpret_cast<float2*>(tileA) + 256;  // [16][16]

    size_t ob = sbase + (size_t)o*1024 + h*32;
    u64* outp2 = reinterpret_cast<u64*>(&g_c2[ob]);
    u64* outp1 = reinterpret_cast<u64*>(&g_c1[ob]);
    float s2 = 0.f, q2 = 0.f, s1 = 0.f, q1 = 0.f;
    #pragma unroll
    for (int p = 0; p < 16; p++) {
        u64 a = acc[p], b = acc1[p];
        outp2[p] = a;
        outp1[p] = b;
        float alo = __uint_as_float((unsigned)(a & 0xffffffffu));
        float ahi = __uint_as_float((unsigned)(a >> 32));
        float blo = __uint_as_float((unsigned)(b & 0xffffffffu));
        float bhi = __uint_as_float((unsigned)(b >> 32));
        s2 += alo + ahi; q2 += alo*alo + ahi*ahi;
        s1 += blo + bhi; q1 += blo*blo + bhi*bhi;
    }
    s2 += __shfl_xor_sync(0xffffffffu, s2, 16);
    q2 += __shfl_xor_sync(0xffffffffu, q2, 16);
    s1 += __shfl_xor_sync(0xffffffffu, s1, 16);
    q1 += __shfl_xor_sync(0xffffffffu, q1, 16);
    if ((tid & 31) < 16) {
        red2[(tid >> 5)*16 + o] = make_float2(s2, q2);
        red1[(tid >> 5)*16 + o] = make_float2(s1, q1);
    }
    __syncthreads();
    if (tid < 32) {
        int oo = tid & 15;
        const float2* src = (tid < 16) ? red2 : red1;
        float S = 0.f, Q = 0.f;
        #pragma unroll
        for (int wd = 0; wd < 16; wd++) { S += src[wd*16 + oo].x; Q += src[wd*16 + oo].y; }
        float2* dst = (tid < 16) ? g_part_c2 : g_part_c1;
        dst[(nb*16 + oo)*16 + tb] = make_float2(S, Q);
    }
}

// ============================================================
// K5: inline inv/c1/c2 stats + out = BN(rec)+BN(c1)+BN(c2). float4.
// ============================================================
__global__ void k_final(float* __restrict__ out,
                        const float* __restrict__ gi, const float* __restrict__ bi,
                        const float* __restrict__ g1, const float* __restrict__ b1,
                        const float* __restrict__ g2, const float* __restrict__ b2) {
    int blk = blockIdx.x, t = threadIdx.x;
    int ch = blk & 255;
    __shared__ float2 cf[3];
    if (t < 48) {
        int w_ = t >> 4, slot = t & 15;
        const float2* part = (w_ == 0) ? g_part_inv : (w_ == 1) ? g_part_c1 : g_part_c2;
        float2 p = part[ch*16 + slot];
        float s = p.x, q = p.y;
        unsigned mask = (t < 32) ? 0xffffffffu : 0x0000ffffu;
        #pragma unroll
        for (int off = 8; off; off >>= 1) {
            s += __shfl_down_sync(mask, s, off, 16);
            q += __shfl_down_sync(mask, q, off, 16);
        }
        if (slot == 0) {
            float mean = s * (1.0f/16384.0f);
            float var  = q * (1.0f/16384.0f) - mean*mean;
            float gg = (w_ == 0) ? gi[ch] : (w_ == 1) ? g1[ch] : g2[ch];
            float bb = (w_ == 0) ? bi[ch] : (w_ == 1) ? b1[ch] : b2[ch];
            float a = gg * rsqrtf(var + 1e-5f);
            cf[w_] = make_float2(a, bb - mean*a);
        }
    }
    __syncthreads();

    size_t base = (size_t)blk * 1024 + t * 4;
    float4 r  = *reinterpret_cast<const float4*>(&g_rec[base]);
    float4 u1 = *reinterpret_cast<const float4*>(&g_c1[base]);
    float4 u2 = *reinterpret_cast<const float4*>(&g_c2[base]);
    float2 A = cf[0], B = cf[1], C = cf[2];
    float4 o;
    o.x = (r.x*A.x + A.y) + (u1.x*B.x + B.y) + (u2.x*C.x + C.y);
    o.y = (r.y*A.x + A.y) + (u1.y*B.x + B.y) + (u2.y*C.x + C.y);
    o.z = (r.z*A.x + A.y) + (u1.z*B.x + B.y) + (u2.z*C.x + C.y);
    o.w = (r.w*A.x + A.y) + (u1.w*B.x + B.y) + (u2.w*C.x + C.y);
    *reinterpret_cast<float4*>(&out[base]) = o;
}

// ============================================================
extern "C" void kernel_launch(void* const* d_in, const int* in_sizes, int n_in,
                              void* d_out, int out_size) {
    const float* x        = (const float*)d_in[0];
    const float* haar_w   = (const float*)d_in[1];
    const float* conv1_w  = (const float*)d_in[2];
    const float* conv2_w  = (const float*)d_in[4];
    const float* bn_fwd_g = (const float*)d_in[6];
    const float* bn_fwd_b = (const float*)d_in[7];
    const float* bn_mul_g = (const float*)d_in[8];
    const float* bn_mul_b = (const float*)d_in[9];
    const float* bn_inv_g = (const float*)d_in[10];
    const float* bn_inv_b = (const float*)d_in[11];
    const float* bn_c1_g  = (const float*)d_in[12];
    const float* bn_c1_b  = (const float*)d_in[13];
    const float* bn_c2_g  = (const float*)d_in[14];
    const float* bn_c2_b  = (const float*)d_in[15];
    float* out = (float*)d_out;

    k_lif_haarw<<<2048, 256>>>(x);
    k_haarh_gate<<<4096, 256>>>(bn_fwd_g, bn_fwd_b);
    k_mix_inv<<<256, 256>>>(haar_w, bn_mul_g, bn_mul_b);
    k_convs<<<256, 512>>>(conv2_w, conv1_w);
    k_final<<<4096, 256>>>(out, bn_inv_g, bn_inv_b,
                           bn_c1_g, bn_c1_b, bn_c2_g, bn_c2_b);
}

// round 10
// speedup vs baseline: 1.0241x; 1.0241x over previous
#include <cuda_runtime.h>
#include <math.h>

#define RS2 0.70710678f // 1/sqrt(2)

typedef unsigned long long u64;

// packed f32x2 FMA (lanewise fp32 fma): d = a*b + d
#define FMA2(d, a, b) asm("fma.rn.f32x2 %0, %1, %2, %0;" : "+l"(d) : "l"(a), "l"(b))

__device__ __forceinline__ u64 dup2(float w) {
    u64 r;
    asm("mov.b64 %0, {%1, %1};" : "=l"(r) : "r"(__float_as_uint(w)));
    return r;
}

// ---- scratch (device globals; no allocation allowed) ----
__device__ float g_s  [4*4*256*32*32];      // spikes (0/1)
__device__ float g_l1 [16*512*32*16];       // pre-BN level-1 coeffs
__device__ float g_l2 [16*1024*16*16];      // pre-BN level-2 coeffs
__device__ float g_rec[16*256*32*32];       // pre-BN reconstruction
__device__ float g_c1 [16*256*32*32];       // pre-BN conv1 out
__device__ float g_c2 [16*256*32*32];       // pre-BN conv2 out
// per-(channel, slot) partial (sum, sumsq) — fixed slots => deterministic
__device__ float2 g_part_fwd[512*8];
__device__ float2 g_part_mul[1024*16];
__device__ float2 g_part_inv[256*16];
__device__ float2 g_part_c1 [256*16];
__device__ float2 g_part_c2 [256*16];

// ============================================================
// K1: LIF over T + Haar along W + L1 gate + bn_fwd partials
// ============================================================
__global__ void k_lif_haarw(const float* __restrict__ x) {
    int blk = blockIdx.x, t = threadIdx.x;
    int idx = blk * 256 + t;
    int wp = idx & 15;
    int h  = (idx >> 4) & 31;
    int c  = (idx >> 9) & 255;
    int b  = idx >> 17;

    float v0 = 0.f, v1 = 0.f;
    float4 ps = make_float4(0.f, 0.f, 0.f, 0.f);
    #pragma unroll
    for (int tt = 0; tt < 4; tt++) {
        size_t base = ((((size_t)tt*4 + b)*256 + c)*32 + h)*32 + 2*wp;
        float2 xx = *reinterpret_cast<const float2*>(&x[base]);
        v0 += (xx.x - v0) * 0.5f;
        float s0 = (v0 >= 1.0f) ? 1.0f : 0.0f;
        v0 *= (1.0f - s0);
        v1 += (xx.y - v1) * 0.5f;
        float s1 = (v1 >= 1.0f) ? 1.0f : 0.0f;
        v1 *= (1.0f - s1);
        *reinterpret_cast<float2*>(&g_s[base]) = make_float2(s0, s1);

        float low  = RS2 * (s0 + s1);
        float high = RS2 * (s0 - s1);
        if (fabsf(low)  < 0.5f) low  = 0.f;
        if (fabsf(high) < 0.5f) high = 0.f;
        int tb = tt*4 + b;
        size_t l1b = (((size_t)tb*512 + c)*32 + h)*16 + wp;
        g_l1[l1b]          = low;
        g_l1[l1b + 131072] = high;
        ps.x += low;  ps.y += low*low;
        ps.z += high; ps.w += high*high;
    }
    #pragma unroll
    for (int off = 16; off; off >>= 1) {
        ps.x += __shfl_down_sync(0xffffffffu, ps.x, off);
        ps.y += __shfl_down_sync(0xffffffffu, ps.y, off);
        ps.z += __shfl_down_sync(0xffffffffu, ps.z, off);
        ps.w += __shfl_down_sync(0xffffffffu, ps.w, off);
    }
    __shared__ float4 wsum[8];
    if ((t & 31) == 0) wsum[t >> 5] = ps;
    __syncthreads();
    if (t == 0) {
        float4 a = wsum[0];
        #pragma unroll
        for (int i = 1; i < 8; i++) {
            float4 w4 = wsum[i];
            a.x += w4.x; a.y += w4.y; a.z += w4.z; a.w += w4.w;
        }
        int slot = ((blk >> 9) << 1) | (blk & 1);   // b*2 + hhalf
        int cc   = (blk >> 1) & 255;
        g_part_fwd[cc*8 + slot]         = make_float2(a.x, a.y);
        g_part_fwd[(256 + cc)*8 + slot] = make_float2(a.z, a.w);
    }
}

// ============================================================
// K2: inline bn_fwd stats + Haar along H + threshold + band gate
//     + bn_mul partials. block <-> (tb, c)
// ============================================================
__global__ void k_haarh_gate(const float* __restrict__ gf,
                             const float* __restrict__ bf) {
    int tb = blockIdx.x >> 8;
    int c  = blockIdx.x & 255;
    int t  = threadIdx.x;

    __shared__ float2 coef[2];
    if (t < 16) {
        int chn = (t < 8) ? c : 256 + c;
        float2 p = g_part_fwd[chn*8 + (t & 7)];
        float s = p.x, q = p.y;
        #pragma unroll
        for (int off = 4; off; off >>= 1) {
            s += __shfl_down_sync(0xffffu, s, off, 8);
            q += __shfl_down_sync(0xffffu, q, off, 8);
        }
        if ((t & 7) == 0) {
            float mean = s * (1.0f/8192.0f);
            float var  = q * (1.0f/8192.0f) - mean*mean;
            float a = gf[chn] * rsqrtf(var + 1e-5f);
            coef[t >> 3] = make_float2(a, bf[chn] - mean*a);
        }
    }
    __syncthreads();

    int v = t >> 4, w = t & 15;
    float alo = coef[0].x, clo = coef[0].y;
    float ahi = coef[1].x, chi = coef[1].y;

    size_t lo_base = ((size_t)tb*512 + c) * 512;
    size_t hi_base = lo_base + 131072;
    float a0 = g_l1[lo_base + (2*v  )*16 + w] * alo + clo;
    float a1 = g_l1[lo_base + (2*v+1)*16 + w] * alo + clo;
    float b0 = g_l1[hi_base + (2*v  )*16 + w] * ahi + chi;
    float b1 = g_l1[hi_base + (2*v+1)*16 + w] * ahi + chi;

    float LL = RS2 * (a0 + a1);
    float HL = RS2 * (a0 - a1);
    float LH = RS2 * (b0 + b1);
    float HH = RS2 * (b0 - b1);
    if (fabsf(LL) < 0.5f) LL = 0.f;
    if (fabsf(HL) < 0.5f) HL = 0.f;
    if (fabsf(LH) < 0.5f) LH = 0.f;
    if (fabsf(HH) < 0.5f) HH = 0.f;

    float4 vs = make_float4(LL, HL, LH, HH);
    float4 vq = make_float4(LL*LL, HL*HL, LH*LH, HH*HH);
    #pragma unroll
    for (int off = 16; off; off >>= 1) {
        vs.x += __shfl_down_sync(0xffffffffu, vs.x, off);
        vs.y += __shfl_down_sync(0xffffffffu, vs.y, off);
        vs.z += __shfl_down_sync(0xffffffffu, vs.z, off);
        vs.w += __shfl_down_sync(0xffffffffu, vs.w, off);
        vq.x += __shfl_down_sync(0xffffffffu, vq.x, off);
        vq.y += __shfl_down_sync(0xffffffffu, vq.y, off);
        vq.z += __shfl_down_sync(0xffffffffu, vq.z, off);
        vq.w += __shfl_down_sync(0xffffffffu, vq.w, off);
    }
    __shared__ float4 wS[8], wQ[8];
    __shared__ float4 flags;
    if ((t & 31) == 0) { wS[t >> 5] = vs; wQ[t >> 5] = vq; }
    __syncthreads();
    if (t == 0) {
        float4 S = wS[0], Q = wQ[0];
        #pragma unroll
        for (int i = 1; i < 8; i++) {
            float4 a = wS[i], b4 = wQ[i];
            S.x += a.x;  S.y += a.y;  S.z += a.z;  S.w += a.w;
            Q.x += b4.x; Q.y += b4.y; Q.z += b4.z; Q.w += b4.w;
        }
        const float inv = 1.0f / 256.0f;
        float4 f = make_float4(Q.x*inv > 0.01f ? 1.f : 0.f,
                               Q.y*inv > 0.02f ? 1.f : 0.f,
                               Q.z*inv > 0.02f ? 1.f : 0.f,
                               Q.w*inv > 0.05f ? 1.f : 0.f);
        flags = f;
        g_part_mul[(c      )*16 + tb] = make_float2(f.x*S.x, f.x*Q.x);
        g_part_mul[(c + 256)*16 + tb] = make_float2(f.y*S.y, f.y*Q.y);
        g_part_mul[(c + 512)*16 + tb] = make_float2(f.z*S.z, f.z*Q.z);
        g_part_mul[(c + 768)*16 + tb] = make_float2(f.w*S.w, f.w*Q.w);
    }
    __syncthreads();

    size_t ob = (((size_t)tb*1024 + c)*16 + v)*16 + w;
    g_l2[ob]          = LL * flags.x;
    g_l2[ob + 65536]  = HL * flags.y;
    g_l2[ob + 131072] = LH * flags.z;
    g_l2[ob + 196608] = HH * flags.w;
}

// ============================================================
// K3 (fused): bn_mul stats + 16x16 channel mix for all 4 subbands of a
// base group + inverse Haar butterfly + bn_inv partials.
// ============================================================
__global__ void k_mix_inv(const float* __restrict__ hw,
                          const float* __restrict__ gm,
                          const float* __restrict__ bm) {
    int tb = blockIdx.x >> 4;
    int gb = blockIdx.x & 15;
    int t  = threadIdx.x;

    __shared__ float Wsm[4][256];
    __shared__ float sc[64], of[64];
    __shared__ float2 wred[8][16];

    #pragma unroll
    for (int sb = 0; sb < 4; sb++)
        Wsm[sb][t] = hw[(4*sb + (gb >> 2)) * 256 + t];

    {
        int chl = t >> 2, j = t & 3;
        int sb = chl >> 4, d = chl & 15;
        int ch = sb*256 + gb*16 + d;
        float s = 0.f, q = 0.f;
        #pragma unroll
        for (int k = 0; k < 4; k++) {
            float2 p = g_part_mul[ch*16 + j + 4*k];
            s += p.x; q += p.y;
        }
        s += __shfl_down_sync(0xffffffffu, s, 2, 4);
        q += __shfl_down_sync(0xffffffffu, q, 2, 4);
        s += __shfl_down_sync(0xffffffffu, s, 1, 4);
        q += __shfl_down_sync(0xffffffffu, q, 1, 4);
        if (j == 0) {
            float mean = s * (1.0f/4096.0f);
            float var  = q * (1.0f/4096.0f) - mean*mean;
            float a = gm[ch] * rsqrtf(var + 1e-5f);
            sc[chl] = a;
            of[chl] = bm[ch] - mean*a;
        }
    }
    __syncthreads();

    float acc[4][16];
    #pragma unroll
    for (int sb = 0; sb < 4; sb++)
        #pragma unroll
        for (int k = 0; k < 16; k++) acc[sb][k] = 0.f;

    #pragma unroll
    for (int sb = 0; sb < 4; sb++) {
        size_t base = ((size_t)tb*1024 + sb*256 + gb*16) * 256 + t;
        #pragma unroll
        for (int d = 0; d < 16; d++) {
            float in = g_l2[base + (size_t)d*256] * sc[sb*16+d] + of[sb*16+d];
            #pragma unroll
            for (int k = 0; k < 16; k++) acc[sb][k] += in * Wsm[sb][d*16 + k];
        }
    }

    int v = t >> 4, w = t & 15;
    int warp = t >> 5;
    #pragma unroll
    for (int k = 0; k < 16; k++) {
        float LL = acc[0][k], HL = acc[1][k], LH = acc[2][k], HH = acc[3][k];
        float lo0 = RS2*(LL + HL), lo1 = RS2*(LL - HL);
        float hi0 = RS2*(LH + HH), hi1 = RS2*(LH - HH);
        float r00 = RS2*(lo0 + hi0), r01 = RS2*(lo0 - hi0);
        float r10 = RS2*(lo1 + hi1), r11 = RS2*(lo1 - hi1);

        size_t rb = (((size_t)tb*256 + gb*16 + k)*32 + 2*v)*32 + 2*w;
        *reinterpret_cast<float2*>(&g_rec[rb])      = make_float2(r00, r01);
        *reinterpret_cast<float2*>(&g_rec[rb + 32]) = make_float2(r10, r11);

        float s = r00 + r01 + r10 + r11;
        float q = r00*r00 + r01*r01 + r10*r10 + r11*r11;
        #pragma unroll
        for (int off = 16; off; off >>= 1) {
            s += __shfl_down_sync(0xffffffffu, s, off);
            q += __shfl_down_sync(0xffffffffu, q, off);
        }
        if ((t & 31) == 0) wred[warp][k] = make_float2(s, q);
    }
    __syncthreads();
    if (t < 16) {
        float S = 0.f, Q = 0.f;
        #pragma unroll
        for (int wd = 0; wd < 8; wd++) { S += wred[wd][t].x; Q += wred[wd][t].y; }
        g_part_inv[(gb*16 + t)*16 + tb] = make_float2(S, Q);
    }
}

// ============================================================
// K4: grouped 1x1 conv v2 — staged smem (2 phases x 8 ch, row stride 36,
// conflict-free), aligned FFMA2 pairs, acc = 32 regs. + bn_c1 partials.
// block <-> image; thread <-> (o, h).
// ============================================================
#define C1_RS 36
#define C1_CH (32 * C1_RS)   // 1152 floats per channel slab

__global__ __launch_bounds__(512) void k_conv1(const float* __restrict__ w1) {
    int im = blockIdx.x;
    int tb = im >> 4, nb = im & 15;
    __shared__ __align__(16) float tile[8 * C1_CH];  // 36864 B
    __shared__ float Wsm1[256];
    __shared__ float2 red[16][16];
    int tid = threadIdx.x;
    int o = tid & 15, h = tid >> 4;

    if (tid < 256) Wsm1[tid] = w1[tid];
    size_t sbase = ((size_t)tb*256 + nb*16) * 1024;

    u64 acc[16];
    #pragma unroll
    for (int p = 0; p < 16; p++) acc[p] = 0ull;

    for (int ph = 0; ph < 2; ph++) {
        __syncthreads();
        for (int idx4 = tid; idx4 < 2048; idx4 += 512) {
            int ii  = idx4 >> 8;
            int rem = idx4 & 255;
            int hh  = rem >> 3;
            int ww4 = (rem & 7) * 4;
            float4 val = *reinterpret_cast<const float4*>(
                &g_s[sbase + (size_t)(ph*8 + ii)*1024 + hh*32 + ww4]);
            *reinterpret_cast<float4*>(&tile[ii*C1_CH + hh*C1_RS + ww4]) = val;
        }
        __syncthreads();

        #pragma unroll
        for (int i = 0; i < 8; i++) {
            u64 wpk = dup2(Wsm1[o*16 + ph*8 + i]);
            const u64* B64 = reinterpret_cast<const u64*>(&tile[i*C1_CH + h*C1_RS]);
            #pragma unroll
            for (int p = 0; p < 16; p++) FMA2(acc[p], wpk, B64[p]);
        }
    }

    size_t ob = sbase + (size_t)o*1024 + h*32;
    u64* outp = reinterpret_cast<u64*>(&g_c1[ob]);
    float s = 0.f, q = 0.f;
    #pragma unroll
    for (int p = 0; p < 16; p++) {
        u64 a = acc[p];
        outp[p] = a;
        float lo = __uint_as_float((unsigned)(a & 0xffffffffu));
        float hi = __uint_as_float((unsigned)(a >> 32));
        s += lo + hi;
        q += lo*lo + hi*hi;
    }
    s += __shfl_xor_sync(0xffffffffu, s, 16);
    q += __shfl_xor_sync(0xffffffffu, q, 16);
    if ((tid & 31) < 16) red[tid >> 5][o] = make_float2(s, q);
    __syncthreads();
    if (tid < 16) {
        float S = 0.f, Q = 0.f;
        #pragma unroll
        for (int wd = 0; wd < 16; wd++) { S += red[wd][tid].x; Q += red[wd][tid].y; }
        g_part_c1[(nb*16 + tid)*16 + tb] = make_float2(S, Q);
    }
}

// ============================================================
// K5: grouped 3x3 conv v2 (FFMA2). 256-thread blocks, 8 output channels
// per block (grid = 512: image x o-half). Both tiles use row stride 36:
// 4 rows/warp land 4 banks apart -> conflict-free; float4-stage aligned.
// tileA shifted +1 (S-family pairs), tileB unshifted (E-family pairs).
// regs ~80 (no launch_bounds cap pressure) -> 2-3 blocks/SM.
// + bn_c2 partials.
// ============================================================
#define A_RS 36
#define A_CH (34 * A_RS)   // 1224 floats per channel slab

__global__ __launch_bounds__(256) void k_conv2(const float* __restrict__ w2) {
    int blk = blockIdx.x;            // 512 = 256 images x 2 o-halves
    int im = blk >> 1, oh = blk & 1;
    int tb = im >> 4, nb = im & 15;
    __shared__ __align__(16) float tileA[4 * A_CH];  // 19584 B
    __shared__ __align__(16) float tileB[4 * A_CH];  // 19584 B
    __shared__ float Wsm[1152];                      //  4608 B
    __shared__ float2 red[8][8];                     //   512 B
    int tid = threadIdx.x;
    int oo = tid & 7, h = tid >> 3;   // 8 o x 32 rows

    for (int idx = tid; idx < 1152; idx += 256) Wsm[idx] = w2[oh*1152 + idx];
    for (int idx = tid; idx < 4 * A_CH; idx += 256) { tileA[idx] = 0.f; tileB[idx] = 0.f; }

    size_t sbase = ((size_t)tb*256 + nb*16) * 1024;

    u64 acc[16];
    #pragma unroll
    for (int p = 0; p < 16; p++) acc[p] = 0ull;

    for (int ph = 0; ph < 4; ph++) {
        __syncthreads();
        for (int idx4 = tid; idx4 < 1024; idx4 += 256) {
            int ii  = idx4 >> 8;
            int rem = idx4 & 255;
            int hh  = rem >> 3;
            int ww4 = (rem & 7) * 4;
            float4 val = *reinterpret_cast<const float4*>(
                &g_s[sbase + (size_t)(ph*4 + ii)*1024 + hh*32 + ww4]);
            float* dA = &tileA[ii*A_CH + (hh+1)*A_RS + ww4 + 1];
            dA[0] = val.x; dA[1] = val.y; dA[2] = val.z; dA[3] = val.w;
            *reinterpret_cast<float4*>(&tileB[ii*A_CH + (hh+1)*A_RS + ww4]) = val;
        }
        __syncthreads();

        #pragma unroll
        for (int ii = 0; ii < 4; ii++) {
            int ic = ph*4 + ii;
            u64 wpk[3][3];
            #pragma unroll
            for (int ky = 0; ky < 3; ky++)
                #pragma unroll
                for (int kx = 0; kx < 3; kx++)
                    wpk[ky][kx] = dup2(Wsm[oo*144 + ic*9 + ky*3 + kx]);

            #pragma unroll
            for (int ky = 0; ky < 3; ky++) {
                const u64* A64 = reinterpret_cast<const u64*>(
                    &tileA[ii*A_CH + (h + ky)*A_RS]);
                const u64* B64 = reinterpret_cast<const u64*>(
                    &tileB[ii*A_CH + (h + ky)*A_RS]);
                u64 sp = A64[0];
                #pragma unroll
                for (int p = 0; p < 16; p++) {
                    u64 e  = B64[p];
                    u64 sn = A64[p + 1];
                    FMA2(acc[p], wpk[ky][0], sp);
                    FMA2(acc[p], wpk[ky][1], e);
                    FMA2(acc[p], wpk[ky][2], sn);
                    sp = sn;
                }
            }
        }
    }

    // store + bn_c2 partials
    int og = oh*8 + oo;
    size_t ob = sbase + (size_t)og*1024 + h*32;
    u64* outp = reinterpret_cast<u64*>(&g_c2[ob]);
    float s = 0.f, q = 0.f;
    #pragma unroll
    for (int p = 0; p < 16; p++) {
        u64 a = acc[p];
        outp[p] = a;
        float lo = __uint_as_float((unsigned)(a & 0xffffffffu));
        float hi = __uint_as_float((unsigned)(a >> 32));
        s += lo + hi;
        q += lo*lo + hi*hi;
    }
    // warp = 8 oo x 4 h; fold the 4 h-lanes (xor 8, 16)
    s += __shfl_xor_sync(0xffffffffu, s, 8);
    q += __shfl_xor_sync(0xffffffffu, q, 8);
    s += __shfl_xor_sync(0xffffffffu, s, 16);
    q += __shfl_xor_sync(0xffffffffu, q, 16);
    if ((tid & 31) < 8) red[tid >> 5][oo] = make_float2(s, q);
    __syncthreads();
    if (tid < 8) {
        float S = 0.f, Q = 0.f;
        #pragma unroll
        for (int wd = 0; wd < 8; wd++) { S += red[wd][tid].x; Q += red[wd][tid].y; }
        g_part_c2[(nb*16 + oh*8 + tid)*16 + tb] = make_float2(S, Q);
    }
}

// ============================================================
// K6: inline inv/c1/c2 stats + out = BN(rec)+BN(c1)+BN(c2). float4.
// ============================================================
__global__ void k_final(float* __restrict__ out,
                        const float* __restrict__ gi, const float* __restrict__ bi,
                        const float* __restrict__ g1, const float* __restrict__ b1,
                        const float* __restrict__ g2, const float* __restrict__ b2) {
    int blk = blockIdx.x, t = threadIdx.x;
    int ch = blk & 255;
    __shared__ float2 cf[3];
    if (t < 48) {
        int w_ = t >> 4, slot = t & 15;
        const float2* part = (w_ == 0) ? g_part_inv : (w_ == 1) ? g_part_c1 : g_part_c2;
        float2 p = part[ch*16 + slot];
        float s = p.x, q = p.y;
        unsigned mask = (t < 32) ? 0xffffffffu : 0x0000ffffu;
        #pragma unroll
        for (int off = 8; off; off >>= 1) {
            s += __shfl_down_sync(mask, s, off, 16);
            q += __shfl_down_sync(mask, q, off, 16);
        }
        if (slot == 0) {
            float mean = s * (1.0f/16384.0f);
            float var  = q * (1.0f/16384.0f) - mean*mean;
            float gg = (w_ == 0) ? gi[ch] : (w_ == 1) ? g1[ch] : g2[ch];
            float bb = (w_ == 0) ? bi[ch] : (w_ == 1) ? b1[ch] : b2[ch];
            float a = gg * rsqrtf(var + 1e-5f);
            cf[w_] = make_float2(a, bb - mean*a);
        }
    }
    __syncthreads();

    size_t base = (size_t)blk * 1024 + t * 4;
    float4 r  = *reinterpret_cast<const float4*>(&g_rec[base]);
    float4 u1 = *reinterpret_cast<const float4*>(&g_c1[base]);
    float4 u2 = *reinterpret_cast<const float4*>(&g_c2[base]);
    float2 A = cf[0], B = cf[1], C = cf[2];
    float4 o;
    o.x = (r.x*A.x + A.y) + (u1.x*B.x + B.y) + (u2.x*C.x + C.y);
    o.y = (r.y*A.x + A.y) + (u1.y*B.x + B.y) + (u2.y*C.x + C.y);
    o.z = (r.z*A.x + A.y) + (u1.z*B.x + B.y) + (u2.z*C.x + C.y);
    o.w = (r.w*A.x + A.y) + (u1.w*B.x + B.y) + (u2.w*C.x + C.y);
    *reinterpret_cast<float4*>(&out[base]) = o;
}

// ============================================================
extern "C" void kernel_launch(void* const* d_in, const int* in_sizes, int n_in,
                              void* d_out, int out_size) {
    const float* x        = (const float*)d_in[0];
    const float* haar_w   = (const float*)d_in[1];
    const float* conv1_w  = (const float*)d_in[2];
    const float* conv2_w  = (const float*)d_in[4];
    const float* bn_fwd_g = (const float*)d_in[6];
    const float* bn_fwd_b = (const float*)d_in[7];
    const float* bn_mul_g = (const float*)d_in[8];
    const float* bn_mul_b = (const float*)d_in[9];
    const float* bn_inv_g = (const float*)d_in[10];
    const float* bn_inv_b = (const float*)d_in[11];
    const float* bn_c1_g  = (const float*)d_in[12];
    const float* bn_c1_b  = (const float*)d_in[13];
    const float* bn_c2_g  = (const float*)d_in[14];
    const float* bn_c2_b  = (const float*)d_in[15];
    float* out = (float*)d_out;

    k_lif_haarw<<<2048, 256>>>(x);
    k_haarh_gate<<<4096, 256>>>(bn_fwd_g, bn_fwd_b);
    k_mix_inv<<<256, 256>>>(haar_w, bn_mul_g, bn_mul_b);
    k_conv1<<<256, 512>>>(conv1_w);
    k_conv2<<<512, 256>>>(conv2_w);
    k_final<<<4096, 256>>>(out, bn_inv_g, bn_inv_b,
                           bn_c1_g, bn_c1_b, bn_c2_g, bn_c2_b);
}

// round 12
// speedup vs baseline: 1.3034x; 1.2727x over previous
#include <cuda_runtime.h>
#include <math.h>

#define RS2 0.70710678f // 1/sqrt(2)

typedef unsigned long long u64;

// packed f32x2 FMA (lanewise fp32 fma): d = a*b + d
#define FMA2(d, a, b) asm("fma.rn.f32x2 %0, %1, %2, %0;" : "+l"(d) : "l"(a), "l"(b))

__device__ __forceinline__ u64 dup2(float w) {
    u64 r;
    asm("mov.b64 %0, {%1, %1};" : "=l"(r) : "r"(__float_as_uint(w)));
    return r;
}

// ---- scratch (device globals; no allocation allowed) ----
__device__ float g_s  [4*4*256*32*32];      // spikes (0/1)
__device__ float g_l1 [16*512*32*16];       // pre-BN level-1 coeffs
__device__ float g_l2 [16*1024*16*16];      // pre-BN level-2 coeffs
__device__ float g_rec[16*256*32*32];       // pre-BN reconstruction
__device__ float g_c1 [16*256*32*32];       // pre-BN conv1 out
__device__ float g_c2 [16*256*32*32];       // pre-BN conv2 out
// per-(channel, slot) partial (sum, sumsq) — fixed slots => deterministic
__device__ float2 g_part_fwd[512*8];
__device__ float2 g_part_mul[1024*16];
__device__ float2 g_part_inv[256*16];
__device__ float2 g_part_c1 [256*32];
__device__ float2 g_part_c2 [256*32];

// ============================================================
// K1: LIF over T + Haar along W + L1 gate + bn_fwd partials
// ============================================================
__global__ void k_lif_haarw(const float* __restrict__ x) {
    int blk = blockIdx.x, t = threadIdx.x;
    int idx = blk * 256 + t;
    int wp = idx & 15;
    int h  = (idx >> 4) & 31;
    int c  = (idx >> 9) & 255;
    int b  = idx >> 17;

    float v0 = 0.f, v1 = 0.f;
    float4 ps = make_float4(0.f, 0.f, 0.f, 0.f);
    #pragma unroll
    for (int tt = 0; tt < 4; tt++) {
        size_t base = ((((size_t)tt*4 + b)*256 + c)*32 + h)*32 + 2*wp;
        float2 xx = *reinterpret_cast<const float2*>(&x[base]);
        v0 += (xx.x - v0) * 0.5f;
        float s0 = (v0 >= 1.0f) ? 1.0f : 0.0f;
        v0 *= (1.0f - s0);
        v1 += (xx.y - v1) * 0.5f;
        float s1 = (v1 >= 1.0f) ? 1.0f : 0.0f;
        v1 *= (1.0f - s1);
        *reinterpret_cast<float2*>(&g_s[base]) = make_float2(s0, s1);

        float low  = RS2 * (s0 + s1);
        float high = RS2 * (s0 - s1);
        if (fabsf(low)  < 0.5f) low  = 0.f;
        if (fabsf(high) < 0.5f) high = 0.f;
        int tb = tt*4 + b;
        size_t l1b = (((size_t)tb*512 + c)*32 + h)*16 + wp;
        g_l1[l1b]          = low;
        g_l1[l1b + 131072] = high;
        ps.x += low;  ps.y += low*low;
        ps.z += high; ps.w += high*high;
    }
    #pragma unroll
    for (int off = 16; off; off >>= 1) {
        ps.x += __shfl_down_sync(0xffffffffu, ps.x, off);
        ps.y += __shfl_down_sync(0xffffffffu, ps.y, off);
        ps.z += __shfl_down_sync(0xffffffffu, ps.z, off);
        ps.w += __shfl_down_sync(0xffffffffu, ps.w, off);
    }
    __shared__ float4 wsum[8];
    if ((t & 31) == 0) wsum[t >> 5] = ps;
    __syncthreads();
    if (t == 0) {
        float4 a = wsum[0];
        #pragma unroll
        for (int i = 1; i < 8; i++) {
            float4 w4 = wsum[i];
            a.x += w4.x; a.y += w4.y; a.z += w4.z; a.w += w4.w;
        }
        int slot = ((blk >> 9) << 1) | (blk & 1);   // b*2 + hhalf
        int cc   = (blk >> 1) & 255;
        g_part_fwd[cc*8 + slot]         = make_float2(a.x, a.y);
        g_part_fwd[(256 + cc)*8 + slot] = make_float2(a.z, a.w);
    }
}

// ============================================================
// K2: inline bn_fwd stats + Haar along H + threshold + band gate
//     + bn_mul partials. block <-> (tb, c)
// ============================================================
__global__ void k_haarh_gate(const float* __restrict__ gf,
                             const float* __restrict__ bf) {
    int tb = blockIdx.x >> 8;
    int c  = blockIdx.x & 255;
    int t  = threadIdx.x;

    __shared__ float2 coef[2];
    if (t < 16) {
        int chn = (t < 8) ? c : 256 + c;
        float2 p = g_part_fwd[chn*8 + (t & 7)];
        float s = p.x, q = p.y;
        #pragma unroll
        for (int off = 4; off; off >>= 1) {
            s += __shfl_down_sync(0xffffu, s, off, 8);
            q += __shfl_down_sync(0xffffu, q, off, 8);
        }
        if ((t & 7) == 0) {
            float mean = s * (1.0f/8192.0f);
            float var  = q * (1.0f/8192.0f) - mean*mean;
            float a = gf[chn] * rsqrtf(var + 1e-5f);
            coef[t >> 3] = make_float2(a, bf[chn] - mean*a);
        }
    }
    __syncthreads();

    int v = t >> 4, w = t & 15;
    float alo = coef[0].x, clo = coef[0].y;
    float ahi = coef[1].x, chi = coef[1].y;

    size_t lo_base = ((size_t)tb*512 + c) * 512;
    size_t hi_base = lo_base + 131072;
    float a0 = g_l1[lo_base + (2*v  )*16 + w] * alo + clo;
    float a1 = g_l1[lo_base + (2*v+1)*16 + w] * alo + clo;
    float b0 = g_l1[hi_base + (2*v  )*16 + w] * ahi + chi;
    float b1 = g_l1[hi_base + (2*v+1)*16 + w] * ahi + chi;

    float LL = RS2 * (a0 + a1);
    float HL = RS2 * (a0 - a1);
    float LH = RS2 * (b0 + b1);
    float HH = RS2 * (b0 - b1);
    if (fabsf(LL) < 0.5f) LL = 0.f;
    if (fabsf(HL) < 0.5f) HL = 0.f;
    if (fabsf(LH) < 0.5f) LH = 0.f;
    if (fabsf(HH) < 0.5f) HH = 0.f;

    float4 vs = make_float4(LL, HL, LH, HH);
    float4 vq = make_float4(LL*LL, HL*HL, LH*LH, HH*HH);
    #pragma unroll
    for (int off = 16; off; off >>= 1) {
        vs.x += __shfl_down_sync(0xffffffffu, vs.x, off);
        vs.y += __shfl_down_sync(0xffffffffu, vs.y, off);
        vs.z += __shfl_down_sync(0xffffffffu, vs.z, off);
        vs.w += __shfl_down_sync(0xffffffffu, vs.w, off);
        vq.x += __shfl_down_sync(0xffffffffu, vq.x, off);
        vq.y += __shfl_down_sync(0xffffffffu, vq.y, off);
        vq.z += __shfl_down_sync(0xffffffffu, vq.z, off);
        vq.w += __shfl_down_sync(0xffffffffu, vq.w, off);
    }
    __shared__ float4 wS[8], wQ[8];
    __shared__ float4 flags;
    if ((t & 31) == 0) { wS[t >> 5] = vs; wQ[t >> 5] = vq; }
    __syncthreads();
    if (t == 0) {
        float4 S = wS[0], Q = wQ[0];
        #pragma unroll
        for (int i = 1; i < 8; i++) {
            float4 a = wS[i], b4 = wQ[i];
            S.x += a.x;  S.y += a.y;  S.z += a.z;  S.w += a.w;
            Q.x += b4.x; Q.y += b4.y; Q.z += b4.z; Q.w += b4.w;
        }
        const float inv = 1.0f / 256.0f;
        float4 f = make_float4(Q.x*inv > 0.01f ? 1.f : 0.f,
                               Q.y*inv > 0.02f ? 1.f : 0.f,
                               Q.z*inv > 0.02f ? 1.f : 0.f,
                               Q.w*inv > 0.05f ? 1.f : 0.f);
        flags = f;
        g_part_mul[(c      )*16 + tb] = make_float2(f.x*S.x, f.x*Q.x);
        g_part_mul[(c + 256)*16 + tb] = make_float2(f.y*S.y, f.y*Q.y);
        g_part_mul[(c + 512)*16 + tb] = make_float2(f.z*S.z, f.z*Q.z);
        g_part_mul[(c + 768)*16 + tb] = make_float2(f.w*S.w, f.w*Q.w);
    }
    __syncthreads();

    size_t ob = (((size_t)tb*1024 + c)*16 + v)*16 + w;
    g_l2[ob]          = LL * flags.x;
    g_l2[ob + 65536]  = HL * flags.y;
    g_l2[ob + 131072] = LH * flags.z;
    g_l2[ob + 196608] = HH * flags.w;
}

// ============================================================
// K3 (fused): bn_mul stats + 16x16 channel mix for all 4 subbands of a
// base group + inverse Haar butterfly + bn_inv partials.
// ============================================================
__global__ void k_mix_inv(const float* __restrict__ hw,
                          const float* __restrict__ gm,
                          const float* __restrict__ bm) {
    int tb = blockIdx.x >> 4;
    int gb = blockIdx.x & 15;
    int t  = threadIdx.x;

    __shared__ float Wsm[4][256];
    __shared__ float sc[64], of[64];
    __shared__ float2 wred[8][16];

    #pragma unroll
    for (int sb = 0; sb < 4; sb++)
        Wsm[sb][t] = hw[(4*sb + (gb >> 2)) * 256 + t];

    {
        int chl = t >> 2, j = t & 3;
        int sb = chl >> 4, d = chl & 15;
        int ch = sb*256 + gb*16 + d;
        float s = 0.f, q = 0.f;
        #pragma unroll
        for (int k = 0; k < 4; k++) {
            float2 p = g_part_mul[ch*16 + j + 4*k];
            s += p.x; q += p.y;
        }
        s += __shfl_down_sync(0xffffffffu, s, 2, 4);
        q += __shfl_down_sync(0xffffffffu, q, 2, 4);
        s += __shfl_down_sync(0xffffffffu, s, 1, 4);
        q += __shfl_down_sync(0xffffffffu, q, 1, 4);
        if (j == 0) {
            float mean = s * (1.0f/4096.0f);
            float var  = q * (1.0f/4096.0f) - mean*mean;
            float a = gm[ch] * rsqrtf(var + 1e-5f);
            sc[chl] = a;
            of[chl] = bm[ch] - mean*a;
        }
    }
    __syncthreads();

    float acc[4][16];
    #pragma unroll
    for (int sb = 0; sb < 4; sb++)
        #pragma unroll
        for (int k = 0; k < 16; k++) acc[sb][k] = 0.f;

    #pragma unroll
    for (int sb = 0; sb < 4; sb++) {
        size_t base = ((size_t)tb*1024 + sb*256 + gb*16) * 256 + t;
        #pragma unroll
        for (int d = 0; d < 16; d++) {
            float in = g_l2[base + (size_t)d*256] * sc[sb*16+d] + of[sb*16+d];
            #pragma unroll
            for (int k = 0; k < 16; k++) acc[sb][k] += in * Wsm[sb][d*16 + k];
        }
    }

    int v = t >> 4, w = t & 15;
    int warp = t >> 5;
    #pragma unroll
    for (int k = 0; k < 16; k++) {
        float LL = acc[0][k], HL = acc[1][k], LH = acc[2][k], HH = acc[3][k];
        float lo0 = RS2*(LL + HL), lo1 = RS2*(LL - HL);
        float hi0 = RS2*(LH + HH), hi1 = RS2*(LH - HH);
        float r00 = RS2*(lo0 + hi0), r01 = RS2*(lo0 - hi0);
        float r10 = RS2*(lo1 + hi1), r11 = RS2*(lo1 - hi1);

        size_t rb = (((size_t)tb*256 + gb*16 + k)*32 + 2*v)*32 + 2*w;
        *reinterpret_cast<float2*>(&g_rec[rb])      = make_float2(r00, r01);
        *reinterpret_cast<float2*>(&g_rec[rb + 32]) = make_float2(r10, r11);

        float s = r00 + r01 + r10 + r11;
        float q = r00*r00 + r01*r01 + r10*r10 + r11*r11;
        #pragma unroll
        for (int off = 16; off; off >>= 1) {
            s += __shfl_down_sync(0xffffffffu, s, off);
            q += __shfl_down_sync(0xffffffffu, q, off);
        }
        if ((t & 31) == 0) wred[warp][k] = make_float2(s, q);
    }
    __syncthreads();
    if (t < 16) {
        float S = 0.f, Q = 0.f;
        #pragma unroll
        for (int wd = 0; wd < 8; wd++) { S += wred[wd][t].x; Q += wred[wd][t].y; }
        g_part_inv[(gb*16 + t)*16 + tb] = make_float2(S, Q);
    }
}

// ============================================================
// K4: grouped 1x1 conv v3 — direct LDG, no staging. 512 blocks x 256 thr,
// thread <-> one pixel pair; 16 coalesced float2 loads (MLP=16), weights
// broadcast from smem, 32 scalar acc regs. + bn_c1 partials (32 slots).
// ============================================================
__global__ __launch_bounds__(256) void k_conv1(const float* __restrict__ w1) {
    int blk = blockIdx.x;                 // 512 = 256 images x 2 halves
    int im = blk >> 1, half = blk & 1;
    int tb = im >> 4, nb = im & 15;
    __shared__ float Wsm[256];
    __shared__ float2 wred[8][16];
    int tid = threadIdx.x;
    Wsm[tid] = w1[tid];
    __syncthreads();

    size_t sbase = (size_t)im * 16384;    // 16 ch * 1024 px
    int p = half*256 + tid;               // pair index in image

    float accx[16], accy[16];
    #pragma unroll
    for (int o = 0; o < 16; o++) { accx[o] = 0.f; accy[o] = 0.f; }

    #pragma unroll
    for (int i = 0; i < 16; i++) {
        float2 v = *reinterpret_cast<const float2*>(&g_s[sbase + (size_t)i*1024 + p*2]);
        #pragma unroll
        for (int o = 0; o < 16; o++) {
            float w = Wsm[o*16 + i];
            accx[o] += w * v.x;
            accy[o] += w * v.y;
        }
    }

    #pragma unroll
    for (int o = 0; o < 16; o++)
        *reinterpret_cast<float2*>(&g_c1[sbase + (size_t)o*1024 + p*2]) =
            make_float2(accx[o], accy[o]);

    // stats: per-o warp reduce then cross-warp
    #pragma unroll
    for (int o = 0; o < 16; o++) {
        float s = accx[o] + accy[o];
        float q = accx[o]*accx[o] + accy[o]*accy[o];
        #pragma unroll
        for (int off = 16; off; off >>= 1) {
            s += __shfl_down_sync(0xffffffffu, s, off);
            q += __shfl_down_sync(0xffffffffu, q, off);
        }
        if ((tid & 31) == 0) wred[tid >> 5][o] = make_float2(s, q);
    }
    __syncthreads();
    if (tid < 16) {
        float S = 0.f, Q = 0.f;
        #pragma unroll
        for (int wd = 0; wd < 8; wd++) { S += wred[wd][tid].x; Q += wred[wd][tid].y; }
        g_part_c1[(nb*16 + tid)*32 + tb*2 + half] = make_float2(S, Q);
    }
}

// ============================================================
// K5: grouped 3x3 conv v3 (FFMA2). grid 1024 = im x oh(2) x hh(2).
// 256 thr = 8 oo x 2 wh x 16 h: each thread 8 output pairs (acc 16 regs).
// Half-height tiles (18 rows incl. halo, stride 36, conflict-free),
// tileA shifted +1 (S pairs), tileB unshifted (E pairs). Weights smem
// transposed [ic*9+k][oo]. + bn_c2 partials (32 slots; wh folded in-block).
// ============================================================
#define A_RS 36
#define TCH18 (18 * A_RS)   // 648 floats per channel slab

__global__ __launch_bounds__(256) void k_conv2(const float* __restrict__ w2) {
    int blk = blockIdx.x;                 // 1024
    int im = blk >> 2;
    int oh = (blk >> 1) & 1;
    int hh = blk & 1;
    int tb = im >> 4, nb = im & 15;
    __shared__ __align__(16) float tileA[4 * TCH18];  // 10368 B
    __shared__ __align__(16) float tileB[4 * TCH18];  // 10368 B
    __shared__ float Wsmt[1152];                      //  4608 B  [ic*9+k][oo]
    __shared__ float2 red[8][8];
    int tid = threadIdx.x;
    int oo = tid & 7;
    int wh = (tid >> 3) & 1;
    int h  = tid >> 4;                    // 0..15

    for (int idx = tid; idx < 1152; idx += 256) {
        int o8 = idx & 7, rest = idx >> 3;          // rest = ic*9+k
        Wsmt[idx] = w2[(oh*8 + o8)*144 + rest];
    }
    for (int idx = tid; idx < 4*TCH18; idx += 256) { tileA[idx] = 0.f; tileB[idx] = 0.f; }

    size_t sbase = (size_t)im * 16384;
    int base = wh * 8;                    // u64 pair offset within row

    u64 acc[8];
    #pragma unroll
    for (int pl = 0; pl < 8; pl++) acc[pl] = 0ull;

    for (int ph = 0; ph < 4; ph++) {
        __syncthreads();
        // stage 4 channels x 18 rows (rows 16hh-1 .. 16hh+16; halo zeros stay)
        for (int idx = tid; idx < 576; idx += 256) {
            int ii  = idx / 144;
            int rem = idx - ii*144;
            int rr  = rem >> 3;                      // local row 0..17
            int ww4 = (rem & 7) * 4;
            int r = 16*hh + rr - 1;
            if (r >= 0 && r < 32) {
                float4 val = *reinterpret_cast<const float4*>(
                    &g_s[sbase + (size_t)(ph*4 + ii)*1024 + r*32 + ww4]);
                float* dA = &tileA[ii*TCH18 + rr*A_RS + ww4 + 1];
                dA[0] = val.x; dA[1] = val.y; dA[2] = val.z; dA[3] = val.w;
                *reinterpret_cast<float4*>(&tileB[ii*TCH18 + rr*A_RS + ww4]) = val;
            }
        }
        __syncthreads();

        #pragma unroll
        for (int ii = 0; ii < 4; ii++) {
            int ic = ph*4 + ii;
            u64 wpk[9];
            #pragma unroll
            for (int k = 0; k < 9; k++) wpk[k] = dup2(Wsmt[(ic*9 + k)*8 + oo]);

            #pragma unroll
            for (int ky = 0; ky < 3; ky++) {
                const u64* A64 = reinterpret_cast<const u64*>(
                    &tileA[ii*TCH18 + (h + ky)*A_RS]);
                const u64* B64 = reinterpret_cast<const u64*>(
                    &tileB[ii*TCH18 + (h + ky)*A_RS]);
                u64 sp = A64[base];
                #pragma unroll
                for (int pl = 0; pl < 8; pl++) {
                    u64 e  = B64[base + pl];
                    u64 sn = A64[base + pl + 1];
                    FMA2(acc[pl], wpk[ky*3 + 0], sp);
                    FMA2(acc[pl], wpk[ky*3 + 1], e);
                    FMA2(acc[pl], wpk[ky*3 + 2], sn);
                    sp = sn;
                }
            }
        }
    }

    // store + bn_c2 partials
    int h_out = 16*hh + h;
    int og = oh*8 + oo;
    size_t ob = sbase + (size_t)og*1024 + h_out*32 + wh*16;
    u64* outp = reinterpret_cast<u64*>(&g_c2[ob]);
    float s = 0.f, q = 0.f;
    #pragma unroll
    for (int pl = 0; pl < 8; pl++) {
        u64 a = acc[pl];
        outp[pl] = a;
        float lo = __uint_as_float((unsigned)(a & 0xffffffffu));
        float hi = __uint_as_float((unsigned)(a >> 32));
        s += lo + hi;
        q += lo*lo + hi*hi;
    }
    // lane = (h&1)*16 + wh*8 + oo: fold h-pair (xor16) then wh (xor8)
    s += __shfl_xor_sync(0xffffffffu, s, 16);
    q += __shfl_xor_sync(0xffffffffu, q, 16);
    s += __shfl_xor_sync(0xffffffffu, s, 8);
    q += __shfl_xor_sync(0xffffffffu, q, 8);
    if ((tid & 31) < 8) red[tid >> 5][oo] = make_float2(s, q);
    __syncthreads();
    if (tid < 8) {
        float S = 0.f, Q = 0.f;
        #pragma unroll
        for (int wd = 0; wd < 8; wd++) { S += red[wd][tid].x; Q += red[wd][tid].y; }
        g_part_c2[(nb*16 + oh*8 + tid)*32 + tb*2 + hh] = make_float2(S, Q);
    }
}

// ============================================================
// K6: inline inv/c1/c2 stats + out = BN(rec)+BN(c1)+BN(c2). float4.
// c1/c2: 32 slots (one warp each); inv: 16 slots.
// ============================================================
__global__ void k_final(float* __restrict__ out,
                        const float* __restrict__ gi, const float* __restrict__ bi,
                        const float* __restrict__ g1, const float* __restrict__ b1,
                        const float* __restrict__ g2, const float* __restrict__ b2) {
    int blk = blockIdx.x, t = threadIdx.x;
    int ch = blk & 255;
    __shared__ float2 cf[3];
    if (t < 32) {                       // c1: 32 slots
        float2 p = g_part_c1[ch*32 + t];
        float s = p.x, q = p.y;
        #pragma unroll
        for (int off = 16; off; off >>= 1) {
            s += __shfl_down_sync(0xffffffffu, s, off);
            q += __shfl_down_sync(0xffffffffu, q, off);
        }
        if (t == 0) {
            float mean = s * (1.0f/16384.0f);
            float var  = q * (1.0f/16384.0f) - mean*mean;
            float a = g1[ch] * rsqrtf(var + 1e-5f);
            cf[1] = make_float2(a, b1[ch] - mean*a);
        }
    } else if (t < 64) {                // c2: 32 slots
        int lane = t - 32;
        float2 p = g_part_c2[ch*32 + lane];
        float s = p.x, q = p.y;
        #pragma unroll
        for (int off = 16; off; off >>= 1) {
            s += __shfl_down_sync(0xffffffffu, s, off);
            q += __shfl_down_sync(0xffffffffu, q, off);
        }
        if (lane == 0) {
            float mean = s * (1.0f/16384.0f);
            float var  = q * (1.0f/16384.0f) - mean*mean;
            float a = g2[ch] * rsqrtf(var + 1e-5f);
            cf[2] = make_float2(a, b2[ch] - mean*a);
        }
    } else if (t < 80) {                // inv: 16 slots (warp2 lanes 0-15)
        int lane = t - 64;
        float2 p = g_part_inv[ch*16 + lane];
        float s = p.x, q = p.y;
        #pragma unroll
        for (int off = 8; off; off >>= 1) {
            s += __shfl_down_sync(0x0000ffffu, s, off, 16);
            q += __shfl_down_sync(0x0000ffffu, q, off, 16);
        }
        if (lane == 0) {
            float mean = s * (1.0f/16384.0f);
            float var  = q * (1.0f/16384.0f) - mean*mean;
            float a = gi[ch] * rsqrtf(var + 1e-5f);
            cf[0] = make_float2(a, bi[ch] - mean*a);
        }
    }
    __syncthreads();

    size_t base = (size_t)blk * 1024 + t * 4;
    float4 r  = *reinterpret_cast<const float4*>(&g_rec[base]);
    float4 u1 = *reinterpret_cast<const float4*>(&g_c1[base]);
    float4 u2 = *reinterpret_cast<const float4*>(&g_c2[base]);
    float2 A = cf[0], B = cf[1], C = cf[2];
    float4 o;
    o.x = (r.x*A.x + A.y) + (u1.x*B.x + B.y) + (u2.x*C.x + C.y);
    o.y = (r.y*A.x + A.y) + (u1.y*B.x + B.y) + (u2.y*C.x + C.y);
    o.z = (r.z*A.x + A.y) + (u1.z*B.x + B.y) + (u2.z*C.x + C.y);
    o.w = (r.w*A.x + A.y) + (u1.w*B.x + B.y) + (u2.w*C.x + C.y);
    *reinterpret_cast<float4*>(&out[base]) = o;
}

// ============================================================
extern "C" void kernel_launch(void* const* d_in, const int* in_sizes, int n_in,
                              void* d_out, int out_size) {
    const float* x        = (const float*)d_in[0];
    const float* haar_w   = (const float*)d_in[1];
    const float* conv1_w  = (const float*)d_in[2];
    const float* conv2_w  = (const float*)d_in[4];
    const float* bn_fwd_g = (const float*)d_in[6];
    const float* bn_fwd_b = (const float*)d_in[7];
    const float* bn_mul_g = (const float*)d_in[8];
    const float* bn_mul_b = (const float*)d_in[9];
    const float* bn_inv_g = (const float*)d_in[10];
    const float* bn_inv_b = (const float*)d_in[11];
    const float* bn_c1_g  = (const float*)d_in[12];
    const float* bn_c1_b  = (const float*)d_in[13];
    const float* bn_c2_g  = (const float*)d_in[14];
    const float* bn_c2_b  = (const float*)d_in[15];
    float* out = (float*)d_out;

    k_lif_haarw<<<2048, 256>>>(x);
    k_haarh_gate<<<4096, 256>>>(bn_fwd_g, bn_fwd_b);
    k_mix_inv<<<256, 256>>>(haar_w, bn_mul_g, bn_mul_b);
    k_conv1<<<512, 256>>>(conv1_w);
    k_conv2<<<1024, 256>>>(conv2_w);
    k_final<<<4096, 256>>>(out, bn_inv_g, bn_inv_b,
                           bn_c1_g, bn_c1_b, bn_c2_g, bn_c2_b);
}